// round 15
// baseline (speedup 1.0000x reference)
#include <cuda_runtime.h>
#include <cuda_fp16.h>
#include <math.h>

#define BB 2
#define NN 2048
#define CC 256
#define HH 8
#define DHH 32
#define SCALE 0.17677669529663687f  // 1/sqrt(32)
#define CH 256                       // scan chunk size (NN/8)

typedef unsigned long long u64;
typedef unsigned u32;

// ---- scratch ----
__device__ __half g_qh16[BB*HH*NN*DHH];  // [bh][n][d] hi, pre-scaled, PERMUTED cols
__device__ __half g_kh16[BB*HH*NN*DHH];  // [bh][n][d] hi, PERMUTED cols
__device__ __half g_kl16[BB*HH*NN*DHH];  // lo
__device__ __half g_vh16[BB*HH*DHH*NN];  // [bh][d][n] hi (transposed), PERMUTED
__device__ __half g_vl16[BB*HH*DHH*NN];
__device__ float g_v [BB*HH*NN*DHH];     // [bh][n][d] f32 (scan input)
__device__ float g_ctx[BB*NN*CC];
__device__ float g_pm[HH*NN];
__device__ float g_pinv[HH*NN];
__device__ float g_scanF[BB*HH*NN*DHH];
__device__ float g_scanG[BB*HH*NN*DHH];

// fragment-pair permutation: u32 index q (0..15) within a 16-u32 row
// -> position so (t, t+4) pairs are adjacent: r<4 -> 8c+2r, else 8c+2(r-4)+1
__device__ __forceinline__ int permpos(int q) {
    int c = q >> 3, r = q & 7;
    return 8 * c + ((r < 4) ? 2 * r : 2 * (r - 4) + 1);
}

// ---- mma.sync fp16 ----
__device__ __forceinline__ void mma_f16(float d[4], const u32 a[4], u32 b0, u32 b1) {
    asm volatile(
        "mma.sync.aligned.m16n8k16.row.col.f32.f16.f16.f32 "
        "{%0,%1,%2,%3}, {%4,%5,%6,%7}, {%8,%9}, {%0,%1,%2,%3};"
        : "+f"(d[0]), "+f"(d[1]), "+f"(d[2]), "+f"(d[3])
        : "r"(a[0]), "r"(a[1]), "r"(a[2]), "r"(a[3]), "r"(b0), "r"(b1));
}
__device__ __forceinline__ u32 packh2(float lo, float hi) {
    __half2 v = __floats2half2_rn(lo, hi);
    return *(u32*)&v;
}
__device__ __forceinline__ void split2h(float v0, float v1, u32 &hp, u32 &lp) {
    float h0 = __half2float(__float2half_rn(v0));
    float h1 = __half2float(__float2half_rn(v1));
    hp = packh2(h0, h1);
    lp = packh2(v0 - h0, v1 - h1);
}

// ---- bf16 helpers (qkv/proj GEMMs) ----
__device__ __forceinline__ void mma_bf16(float d[4], const u32 a[4], u32 b0, u32 b1) {
    asm volatile(
        "mma.sync.aligned.m16n8k16.row.col.f32.bf16.bf16.f32 "
        "{%0,%1,%2,%3}, {%4,%5,%6,%7}, {%8,%9}, {%0,%1,%2,%3};"
        : "+f"(d[0]), "+f"(d[1]), "+f"(d[2]), "+f"(d[3])
        : "r"(a[0]), "r"(a[1]), "r"(a[2]), "r"(a[3]), "r"(b0), "r"(b1));
}
__device__ __forceinline__ u32 packbf2(float lo, float hi) {
    unsigned short b0, b1;
    asm("cvt.rn.bf16.f32 %0, %1;" : "=h"(b0) : "f"(lo));
    asm("cvt.rn.bf16.f32 %0, %1;" : "=h"(b1) : "f"(hi));
    return (u32)b0 | ((u32)b1 << 16);
}
__device__ __forceinline__ float bf2f(unsigned short b) {
    u32 u = (u32)b << 16;
    return __uint_as_float(u);
}
__device__ __forceinline__ void split2(float v0, float v1, u32 &hp, u32 &lp) {
    u32 hp0 = packbf2(v0, v1);
    float h0 = bf2f((unsigned short)(hp0 & 0xffff));
    float h1 = bf2f((unsigned short)(hp0 >> 16));
    hp = hp0;
    lp = packbf2(v0 - h0, v1 - h1);
}

// ============================================================
// 1) pos softmax row stats, closed form
// ============================================================
__global__ void pos_stats_kernel(const float* __restrict__ Wpos,
                                 const float* __restrict__ bpos) {
    int idx = blockIdx.x * blockDim.x + threadIdx.x;
    if (idx >= HH * NN) return;
    int h = idx / NN, i = idx - h * NN;
    float W0 = Wpos[h], W1 = Wpos[HH + h], bph = bpos[h];
    float apos = W0 + W1;
    float aneg = W1 - W0;
    float fi = (float)i, fM = (float)(NN - 1 - i);
    float mi = fmaxf(0.f, fmaxf(apos * fi, aneg * fM));

    float Sp;
    if (i == 0)            Sp = 0.f;
    else if (apos > 0.f)   Sp = __expf(apos * fi - mi) * expm1f(-apos * fi) / expm1f(-apos);
    else if (apos < 0.f)   Sp = __expf(apos - mi) * expm1f(apos * fi) / expm1f(apos);
    else                   Sp = fi * __expf(-mi);

    float Sn;
    if (i == NN - 1)       Sn = 0.f;
    else if (aneg > 0.f)   Sn = __expf(aneg * fM - mi) * expm1f(-aneg * fM) / expm1f(-aneg);
    else if (aneg < 0.f)   Sn = __expf(aneg - mi) * expm1f(aneg * fM) / expm1f(aneg);
    else                   Sn = fM * __expf(-mi);

    float den = __expf(-mi) + Sp + Sn;
    g_pm[idx]   = bph + mi;
    g_pinv[idx] = 1.f / den;
}

// ============================================================
// 2) QKV GEMM on mma.sync split-bf16 (3-pass); epilogue emits
//    permuted fp16 q(hi), k(hi/lo), vT(hi/lo) + f32 v.
// ============================================================
__global__ void __launch_bounds__(256) qkv_tc_kernel(const float* __restrict__ x,
                                                     const float* __restrict__ Wqk,
                                                     const float* __restrict__ Wv) {
    __shared__ u32 sAh[128 * 20], sAl[128 * 20];
    __shared__ u32 sBh[64 * 20],  sBl[64 * 20];

    int tid = threadIdx.x;
    int w = tid >> 5, lane = tid & 31, g = lane >> 2, t = lane & 3;
    int m0 = blockIdx.x * 128, n0 = blockIdx.y * 64;

    const float* Wsrc; int ldw, coff;
    if (n0 < 512) { Wsrc = Wqk; ldw = 512; coff = n0; }
    else          { Wsrc = Wv;  ldw = 256; coff = n0 - 512; }

    int arow = tid >> 1, ahalf = tid & 1;
    int bn = tid & 63, bkg = tid >> 6;

    float o[8][4] = {};

    for (int kc = 0; kc < 8; kc++) {
        int k0 = kc * 32;
        __syncthreads();
        {
            const float* xs = &x[(size_t)(m0 + arow) * 256 + k0 + ahalf * 16];
            float4 f0 = *(const float4*)xs, f1 = *(const float4*)(xs + 4);
            float4 f2 = *(const float4*)(xs + 8), f3 = *(const float4*)(xs + 12);
            u32 hi[8], lo[8];
            split2(f0.x, f0.y, hi[0], lo[0]); split2(f0.z, f0.w, hi[1], lo[1]);
            split2(f1.x, f1.y, hi[2], lo[2]); split2(f1.z, f1.w, hi[3], lo[3]);
            split2(f2.x, f2.y, hi[4], lo[4]); split2(f2.z, f2.w, hi[5], lo[5]);
            split2(f3.x, f3.y, hi[6], lo[6]); split2(f3.z, f3.w, hi[7], lo[7]);
            uint4* dh = (uint4*)&sAh[arow * 20 + ahalf * 8];
            dh[0] = make_uint4(hi[0], hi[1], hi[2], hi[3]);
            dh[1] = make_uint4(hi[4], hi[5], hi[6], hi[7]);
            uint4* dl = (uint4*)&sAl[arow * 20 + ahalf * 8];
            dl[0] = make_uint4(lo[0], lo[1], lo[2], lo[3]);
            dl[1] = make_uint4(lo[4], lo[5], lo[6], lo[7]);
        }
        {
            float wv[8];
            #pragma unroll
            for (int i = 0; i < 8; i++)
                wv[i] = Wsrc[(size_t)(k0 + bkg * 8 + i) * ldw + coff + bn];
            u32 bh4[4], bl4[4];
            split2(wv[0], wv[1], bh4[0], bl4[0]);
            split2(wv[2], wv[3], bh4[1], bl4[1]);
            split2(wv[4], wv[5], bh4[2], bl4[2]);
            split2(wv[6], wv[7], bh4[3], bl4[3]);
            *(uint4*)&sBh[bn * 20 + bkg * 4] = make_uint4(bh4[0], bh4[1], bh4[2], bh4[3]);
            *(uint4*)&sBl[bn * 20 + bkg * 4] = make_uint4(bl4[0], bl4[1], bl4[2], bl4[3]);
        }
        __syncthreads();

        u32 aH[2][4], aL[2][4];
        int r0 = 16 * w + g;
        #pragma unroll
        for (int c = 0; c < 2; c++) {
            aH[c][0] = sAh[r0 * 20 + 8 * c + t];
            aH[c][1] = sAh[(r0 + 8) * 20 + 8 * c + t];
            aH[c][2] = sAh[r0 * 20 + 8 * c + t + 4];
            aH[c][3] = sAh[(r0 + 8) * 20 + 8 * c + t + 4];
            aL[c][0] = sAl[r0 * 20 + 8 * c + t];
            aL[c][1] = sAl[(r0 + 8) * 20 + 8 * c + t];
            aL[c][2] = sAl[r0 * 20 + 8 * c + t + 4];
            aL[c][3] = sAl[(r0 + 8) * 20 + 8 * c + t + 4];
        }
        #pragma unroll
        for (int j = 0; j < 8; j++) {
            #pragma unroll
            for (int c = 0; c < 2; c++) {
                int base = (8 * j + g) * 20 + 8 * c + t;
                u32 b0 = sBh[base], b1 = sBh[base + 4];
                u32 c0 = sBl[base], c1 = sBl[base + 4];
                mma_bf16(o[j], aH[c], b0, b1);
                mma_bf16(o[j], aH[c], c0, c1);
                mma_bf16(o[j], aL[c], b0, b1);
            }
        }
    }

    int row_a = m0 + 16 * w + g;
    #pragma unroll
    for (int j = 0; j < 8; j++) {
        int c = n0 + 8 * j + 2 * t;
        #pragma unroll
        for (int r = 0; r < 2; r++) {
            int m = row_a + 8 * r;
            float v0 = o[j][2 * r], v1 = o[j][2 * r + 1];
            int b = m >> 11, n = m & (NN - 1);
            if (c < 256) {
                int h = c >> 5, d0 = c & 31;
                int bh = b * HH + h;
                v0 *= SCALE; v1 *= SCALE;
                size_t ui = ((size_t)bh * NN + n) * 16 + permpos(d0 >> 1);
                ((u32*)g_qh16)[ui] = packh2(v0, v1);
            } else if (c < 512) {
                int cc = c - 256; int h = cc >> 5, d0 = cc & 31;
                int bh = b * HH + h;
                u32 hp, lp;
                split2h(v0, v1, hp, lp);
                size_t ui = ((size_t)bh * NN + n) * 16 + permpos(d0 >> 1);
                ((u32*)g_kh16)[ui] = hp;
                ((u32*)g_kl16)[ui] = lp;
            } else {
                int cc = c - 512; int h = cc >> 5, d0 = cc & 31;
                int bh = b * HH + h;
                *(float2*)&g_v[((size_t)bh * NN + n) * DHH + d0] = make_float2(v0, v1);
                __half h0 = __float2half_rn(v0);
                __half h1 = __float2half_rn(v1);
                // vT [d][n]: n-pairs permuted within each 16-u32 group
                int ng = n >> 5, nq = (n >> 1) & 15, nh = n & 1;
                size_t base16 = ((size_t)bh * DHH) * (NN / 2) + (size_t)ng * 16 + permpos(nq);
                __half* vh = (__half*)((u32*)g_vh16 + base16 + (size_t)(NN / 2) * 0);
                // write halves individually (n parity selects half within the u32)
                ((__half*)((u32*)g_vh16 + base16 + (size_t)d0 * (NN / 2)))[nh] = h0;
                ((__half*)((u32*)g_vl16 + base16 + (size_t)d0 * (NN / 2)))[nh] =
                    __float2half_rn(v0 - __half2float(h0));
                ((__half*)((u32*)g_vh16 + base16 + (size_t)(d0 + 1) * (NN / 2)))[nh] = h1;
                ((__half*)((u32*)g_vl16 + base16 + (size_t)(d0 + 1) * (NN / 2)))[nh] =
                    __float2half_rn(v1 - __half2float(h1));
                (void)vh;
            }
        }
    }
}

// ============================================================
// 3) POS path: blocked-parallel exponential scans, 512 threads
// ============================================================
__global__ void __launch_bounds__(512) pos_scan_kernel(const float* __restrict__ Wpos,
                                                       const float* __restrict__ bpos) {
    __shared__ float TFs[8][32], TGs[8][32], AFs[8][32], DGs[8][32];

    int bh = blockIdx.x;
    int h = bh & (HH - 1);
    int tid = threadIdx.x;
    int w = tid >> 5, lane = tid & 31;
    float apos = Wpos[h] + Wpos[HH + h];
    float aneg = Wpos[HH + h] - Wpos[h];
    bool posg = apos > 0.f, negg = aneg > 0.f;
    float rhoF = posg ? 1.f : __expf(apos);
    float rhoG = negg ? 1.f : __expf(aneg);
    float wcF = posg ? -apos : 0.f;
    float wcG = negg ? -aneg : 0.f;
    float usG = negg ? 1.f : rhoG;

    const float* vp = g_v + (size_t)bh * NN * DHH + lane;
    float* fo = g_scanF + (size_t)bh * NN * DHH + lane;
    float* go = g_scanG + (size_t)bh * NN * DHH + lane;

    if (w < 8) {
        int c0 = w * CH;
        float F = 0.f;
        for (int ib = c0; ib < c0 + CH; ib += 8) {
            float vb[8];
            #pragma unroll
            for (int u = 0; u < 8; u++) vb[u] = vp[(ib + u) * DHH];
            #pragma unroll
            for (int u = 0; u < 8; u++) {
                float uu = vb[u] * __expf(wcF * (float)(ib + u));
                F = rhoF * F + uu;
                fo[(ib + u) * DHH] = F;
            }
        }
        TFs[w][lane] = F;
    } else {
        int c0 = (w - 8) * CH;
        float G = 0.f;
        for (int ib = c0 + CH - 1; ib >= c0; ib -= 8) {
            float vb[8];
            #pragma unroll
            for (int u = 0; u < 8; u++) vb[u] = vp[(ib - u) * DHH];
            #pragma unroll
            for (int u = 0; u < 8; u++) {
                int i = ib - u;
                go[i * DHH] = G;
                float uu = usG * vb[u] * __expf(wcG * (float)(NN - 1 - i));
                G = rhoG * G + uu;
            }
        }
        TGs[w - 8][lane] = G;
    }
    __syncthreads();

    if (w == 0) {
        float fF = posg ? 1.f : __expf(apos * (float)CH);
        float A = 0.f;
        #pragma unroll
        for (int c = 0; c < 8; c++) { AFs[c][lane] = A; A = TFs[c][lane] + fF * A; }
    } else if (w == 8) {
        float fG = negg ? 1.f : __expf(aneg * (float)CH);
        float D = 0.f;
        #pragma unroll
        for (int c = 7; c >= 0; c--) { DGs[c][lane] = D; D = TGs[c][lane] + fG * D; }
    }
    __syncthreads();

    int c = w >> 1;
    int c0 = c * CH;
    int cend = c0 + CH;
    int r0 = w * 128;
    float A = AFs[c][lane];
    float D = DGs[c][lane];
    float pfc = posg ? 0.f : apos;
    float gfc = negg ? 0.f : aneg;
    float bph = bpos[h];
    float pp = fmaxf(apos, 0.f), pn = fmaxf(aneg, 0.f);
    const float* pmrow = g_pm + h * NN;
    for (int ib = r0; ib < r0 + 128; ib += 8) {
        float fb[8], gb[8], pmb[8];
        #pragma unroll
        for (int u = 0; u < 8; u++) {
            fb[u]  = fo[(ib + u) * DHH];
            gb[u]  = go[(ib + u) * DHH];
            pmb[u] = pmrow[ib + u];
        }
        #pragma unroll
        for (int u = 0; u < 8; u++) {
            int i = ib + u;
            float Fg = fb[u] + A * __expf(pfc * (float)(i - c0 + 1));
            float Gg = gb[u] + D * __expf(gfc * (float)(cend - 1 - i));
            float c1 = __expf(bph + pp * (float)i - pmb[u]);
            float c2 = __expf(bph + pn * (float)(NN - 1 - i) - pmb[u]);
            fo[i * DHH] = c1 * Fg + c2 * Gg;
        }
    }
}

// ============================================================
// 4) PATCH attention, fp16 mma.sync:
//    QK 2-pass (q_hi only), PV 2-pass; permuted smem, LDS.64 frags,
//    K/V double-buffered, 1 barrier/tile.
// ============================================================
__global__ void __launch_bounds__(256, 2) attn_mma_kernel(const float* __restrict__ gating) {
    __shared__ u32 QsH[128 * 20];
    __shared__ u32 KsH[2][32 * 20], KsL[2][32 * 20];
    __shared__ u32 VsH[2][32 * 20], VsL[2][32 * 20];

    int tid = threadIdx.x;
    int w = tid >> 5, lane = tid & 31, g = lane >> 2, t = lane & 3;
    int qt = blockIdx.x, hidx = blockIdx.y, b = blockIdx.z;
    int bh = b * HH + hidx;
    int q0 = qt * 128;

    const u32* gqh = (const u32*)g_qh16 + (size_t)bh * NN * 16;
    const u32* gkh = (const u32*)g_kh16 + (size_t)bh * NN * 16;
    const u32* gkl = (const u32*)g_kl16 + (size_t)bh * NN * 16;
    const u32* gvh = (const u32*)g_vh16 + (size_t)bh * DHH * (NN / 2);
    const u32* gvl = (const u32*)g_vl16 + (size_t)bh * DHH * (NN / 2);

    // stage Q [128][32] hi (already permuted in gmem)
    {
        int row = tid >> 1, half = tid & 1;
        const uint4* s0 = (const uint4*)(gqh + (size_t)(q0 + row) * 16 + half * 8);
        uint4 v0 = s0[0], v1 = s0[1];
        uint4* d0 = (uint4*)&QsH[row * 20 + half * 8];
        d0[0] = v0; d0[1] = v1;
    }
    // stage K/V tile 0 into buffer 0 (gmem already permuted -> straight copy)
    int srow = tid >> 3, spp = tid & 7;
    {
        *(uint2*)&KsH[0][srow * 20 + spp * 2] = *(const uint2*)(gkh + (size_t)srow * 16 + spp * 2);
        *(uint2*)&KsL[0][srow * 20 + spp * 2] = *(const uint2*)(gkl + (size_t)srow * 16 + spp * 2);
        *(uint2*)&VsH[0][srow * 20 + spp * 2] = *(const uint2*)(gvh + (size_t)srow * (NN / 2) + spp * 2);
        *(uint2*)&VsL[0][srow * 20 + spp * 2] = *(const uint2*)(gvl + (size_t)srow * (NN / 2) + spp * 2);
    }
    __syncthreads();

    // Q fragments (constant across tiles): (a0,a2) and (a1,a3) adjacent
    u32 aQh[2][4];
    {
        int r0 = 16 * w + g;
        #pragma unroll
        for (int c = 0; c < 2; c++) {
            uint2 p0 = *(const uint2*)&QsH[r0 * 20 + 8 * c + 2 * t];
            uint2 p1 = *(const uint2*)&QsH[(r0 + 8) * 20 + 8 * c + 2 * t];
            aQh[c][0] = p0.x; aQh[c][2] = p0.y;
            aQh[c][1] = p1.x; aQh[c][3] = p1.y;
        }
    }

    float o[4][4] = {};
    float lp0 = 0.f, lp1 = 0.f;

    for (int kt = 0; kt < 64; kt++) {
        int buf = kt & 1;
        uint2 pkh, pkl, pvh, pvl;
        if (kt < 63) {
            int k0n = (kt + 1) * 32;
            pkh = *(const uint2*)(gkh + (size_t)(k0n + srow) * 16 + spp * 2);
            pkl = *(const uint2*)(gkl + (size_t)(k0n + srow) * 16 + spp * 2);
            pvh = *(const uint2*)(gvh + (size_t)srow * (NN / 2) + k0n / 2 + spp * 2);
            pvl = *(const uint2*)(gvl + (size_t)srow * (NN / 2) + k0n / 2 + spp * 2);
        }
        // ---- QK: S[16q x 32k], 2-pass (q_hi x k_hi + q_hi x k_lo) ----
        float s[4][4] = {};
        #pragma unroll
        for (int j = 0; j < 4; j++) {
            #pragma unroll
            for (int c = 0; c < 2; c++) {
                int base = (8 * j + g) * 20 + 8 * c + 2 * t;
                uint2 kb = *(const uint2*)&KsH[buf][base];
                uint2 lb = *(const uint2*)&KsL[buf][base];
                mma_f16(s[j], aQh[c], kb.x, kb.y);
                mma_f16(s[j], aQh[c], lb.x, lb.y);
            }
        }
        // ---- exp + P fragments ----
        float e[4][4];
        #pragma unroll
        for (int j = 0; j < 4; j++) {
            e[j][0] = __expf(s[j][0]); e[j][1] = __expf(s[j][1]);
            e[j][2] = __expf(s[j][2]); e[j][3] = __expf(s[j][3]);
            lp0 += e[j][0] + e[j][1];
            lp1 += e[j][2] + e[j][3];
        }
        u32 pa[2][4];
        #pragma unroll
        for (int kc = 0; kc < 2; kc++) {
            int j0 = 2 * kc, j1 = 2 * kc + 1;
            pa[kc][0] = packh2(e[j0][0], e[j0][1]);
            pa[kc][1] = packh2(e[j0][2], e[j0][3]);
            pa[kc][2] = packh2(e[j1][0], e[j1][1]);
            pa[kc][3] = packh2(e[j1][2], e[j1][3]);
        }
        // ---- PV: O[16q x 32d], 2-pass ----
        #pragma unroll
        for (int jj = 0; jj < 4; jj++) {
            #pragma unroll
            for (int kc = 0; kc < 2; kc++) {
                int base = (8 * jj + g) * 20 + 8 * kc + 2 * t;
                uint2 vb = *(const uint2*)&VsH[buf][base];
                uint2 wb = *(const uint2*)&VsL[buf][base];
                mma_f16(o[jj], pa[kc], vb.x, vb.y);
                mma_f16(o[jj], pa[kc], wb.x, wb.y);
            }
        }
        if (kt < 63) {
            int nb = buf ^ 1;
            *(uint2*)&KsH[nb][srow * 20 + spp * 2] = pkh;
            *(uint2*)&KsL[nb][srow * 20 + spp * 2] = pkl;
            *(uint2*)&VsH[nb][srow * 20 + spp * 2] = pvh;
            *(uint2*)&VsL[nb][srow * 20 + spp * 2] = pvl;
            __syncthreads();
        }
    }

    // ---- epilogue ----
    lp0 += __shfl_xor_sync(0xffffffffu, lp0, 1);
    lp0 += __shfl_xor_sync(0xffffffffu, lp0, 2);
    lp1 += __shfl_xor_sync(0xffffffffu, lp1, 1);
    lp1 += __shfl_xor_sync(0xffffffffu, lp1, 2);

    float gv = 1.f / (1.f + __expf(-gating[hidx]));
    int row0 = q0 + 16 * w + g, row1 = row0 + 8;
    float s1a = (1.f - gv) / lp0, s1b = (1.f - gv) / lp1;
    float s2a = gv * g_pinv[hidx * NN + row0];
    float s2b = gv * g_pinv[hidx * NN + row1];

    #pragma unroll
    for (int jj = 0; jj < 4; jj++) {
        int dh = 8 * jj + 2 * t;
        float2 p0 = *(const float2*)&g_scanF[((size_t)bh * NN + row0) * DHH + dh];
        float2 p1 = *(const float2*)&g_scanF[((size_t)bh * NN + row1) * DHH + dh];
        float2 o0 = make_float2(s1a * o[jj][0] + s2a * p0.x, s1a * o[jj][1] + s2a * p0.y);
        float2 o1 = make_float2(s1b * o[jj][2] + s2b * p1.x, s1b * o[jj][3] + s2b * p1.y);
        int col = hidx * 32 + dh;
        *(float2*)&g_ctx[((size_t)b * NN + row0) * CC + col] = o0;
        *(float2*)&g_ctx[((size_t)b * NN + row1) * CC + col] = o1;
    }
}

// ============================================================
// 5) Output projection on mma.sync split-bf16 (3-pass)
// ============================================================
__global__ void __launch_bounds__(256) proj_tc_kernel(const float* __restrict__ Wp,
                                                      const float* __restrict__ bp,
                                                      float* __restrict__ out) {
    __shared__ u32 sAh[128 * 20], sAl[128 * 20];
    __shared__ u32 sBh[64 * 20],  sBl[64 * 20];

    int tid = threadIdx.x;
    int w = tid >> 5, lane = tid & 31, g = lane >> 2, t = lane & 3;
    int m0 = blockIdx.x * 128, n0 = blockIdx.y * 64;

    int arow = tid >> 1, ahalf = tid & 1;
    int bn = tid & 63, bkg = tid >> 6;

    float o[8][4] = {};

    for (int kc = 0; kc < 8; kc++) {
        int k0 = kc * 32;
        __syncthreads();
        {
            const float* xs = &g_ctx[(size_t)(m0 + arow) * 256 + k0 + ahalf * 16];
            float4 f0 = *(const float4*)xs, f1 = *(const float4*)(xs + 4);
            float4 f2 = *(const float4*)(xs + 8), f3 = *(const float4*)(xs + 12);
            u32 hi[8], lo[8];
            split2(f0.x, f0.y, hi[0], lo[0]); split2(f0.z, f0.w, hi[1], lo[1]);
            split2(f1.x, f1.y, hi[2], lo[2]); split2(f1.z, f1.w, hi[3], lo[3]);
            split2(f2.x, f2.y, hi[4], lo[4]); split2(f2.z, f2.w, hi[5], lo[5]);
            split2(f3.x, f3.y, hi[6], lo[6]); split2(f3.z, f3.w, hi[7], lo[7]);
            uint4* dh = (uint4*)&sAh[arow * 20 + ahalf * 8];
            dh[0] = make_uint4(hi[0], hi[1], hi[2], hi[3]);
            dh[1] = make_uint4(hi[4], hi[5], hi[6], hi[7]);
            uint4* dl = (uint4*)&sAl[arow * 20 + ahalf * 8];
            dl[0] = make_uint4(lo[0], lo[1], lo[2], lo[3]);
            dl[1] = make_uint4(lo[4], lo[5], lo[6], lo[7]);
        }
        {
            float wv[8];
            #pragma unroll
            for (int i = 0; i < 8; i++)
                wv[i] = Wp[(size_t)(k0 + bkg * 8 + i) * 256 + n0 + bn];
            u32 bh4[4], bl4[4];
            split2(wv[0], wv[1], bh4[0], bl4[0]);
            split2(wv[2], wv[3], bh4[1], bl4[1]);
            split2(wv[4], wv[5], bh4[2], bl4[2]);
            split2(wv[6], wv[7], bh4[3], bl4[3]);
            *(uint4*)&sBh[bn * 20 + bkg * 4] = make_uint4(bh4[0], bh4[1], bh4[2], bh4[3]);
            *(uint4*)&sBl[bn * 20 + bkg * 4] = make_uint4(bl4[0], bl4[1], bl4[2], bl4[3]);
        }
        __syncthreads();

        u32 aH[2][4], aL[2][4];
        int r0 = 16 * w + g;
        #pragma unroll
        for (int c = 0; c < 2; c++) {
            aH[c][0] = sAh[r0 * 20 + 8 * c + t];
            aH[c][1] = sAh[(r0 + 8) * 20 + 8 * c + t];
            aH[c][2] = sAh[r0 * 20 + 8 * c + t + 4];
            aH[c][3] = sAh[(r0 + 8) * 20 + 8 * c + t + 4];
            aL[c][0] = sAl[r0 * 20 + 8 * c + t];
            aL[c][1] = sAl[(r0 + 8) * 20 + 8 * c + t];
            aL[c][2] = sAl[r0 * 20 + 8 * c + t + 4];
            aL[c][3] = sAl[(r0 + 8) * 20 + 8 * c + t + 4];
        }
        #pragma unroll
        for (int j = 0; j < 8; j++) {
            #pragma unroll
            for (int c = 0; c < 2; c++) {
                int base = (8 * j + g) * 20 + 8 * c + t;
                u32 b0 = sBh[base], b1 = sBh[base + 4];
                u32 c0 = sBl[base], c1 = sBl[base + 4];
                mma_bf16(o[j], aH[c], b0, b1);
                mma_bf16(o[j], aH[c], c0, c1);
                mma_bf16(o[j], aL[c], b0, b1);
            }
        }
    }

    int row_a = m0 + 16 * w + g;
    #pragma unroll
    for (int j = 0; j < 8; j++) {
        int c = n0 + 8 * j + 2 * t;
        float2 bpc = *(const float2*)&bp[c];
        #pragma unroll
        for (int r = 0; r < 2; r++) {
            int m = row_a + 8 * r;
            *(float2*)&out[(size_t)m * 256 + c] =
                make_float2(o[j][2 * r] + bpc.x, o[j][2 * r + 1] + bpc.y);
        }
    }
}

// ============================================================
extern "C" void kernel_launch(void* const* d_in, const int* in_sizes, int n_in,
                              void* d_out, int out_size) {
    const float* x     = (const float*)d_in[0];
    const float* Wqk   = (const float*)d_in[1];
    const float* Wv    = (const float*)d_in[2];
    const float* Wproj = (const float*)d_in[3];
    const float* bproj = (const float*)d_in[4];
    const float* Wpos  = (const float*)d_in[5];
    const float* bpos  = (const float*)d_in[6];
    const float* gate  = (const float*)d_in[7];
    float* out = (float*)d_out;

    pos_stats_kernel<<<(HH * NN + 255) / 256, 256>>>(Wpos, bpos);
    qkv_tc_kernel<<<dim3(BB * NN / 128, 12), 256>>>(x, Wqk, Wv);
    pos_scan_kernel<<<BB * HH, 512>>>(Wpos, bpos);
    attn_mma_kernel<<<dim3(NN / 128, HH, BB), 256>>>(gate);
    proj_tc_kernel<<<dim3(BB * NN / 128, 4), 256>>>(Wproj, bproj, out);
}

// round 16
// speedup vs baseline: 1.1568x; 1.1568x over previous
#include <cuda_runtime.h>
#include <cuda_fp16.h>
#include <math.h>

#define BB 2
#define NN 2048
#define CC 256
#define HH 8
#define DHH 32
#define SCALE 0.17677669529663687f  // 1/sqrt(32)
#define CH 256                       // scan chunk size (NN/8)

typedef unsigned long long u64;
typedef unsigned u32;

// ---- scratch ----
__device__ __half g_qh16[BB*HH*NN*DHH];  // [bh][n][d] fp16, pre-scaled
__device__ __half g_kh16[BB*HH*NN*DHH];  // [bh][n][d] hi
__device__ __half g_kl16[BB*HH*NN*DHH];  // lo
__device__ __half g_vh16[BB*HH*DHH*NN];  // [bh][d][n] hi (transposed)
__device__ __half g_vl16[BB*HH*DHH*NN];
__device__ float g_v [BB*HH*NN*DHH];     // [bh][n][d] f32 (scan input)
__device__ float g_ctx[BB*NN*CC];
__device__ float g_pm[HH*NN];
__device__ float g_pinv[HH*NN];
__device__ float g_scanF[BB*HH*NN*DHH];
__device__ float g_scanG[BB*HH*NN*DHH];

// ---- mma.sync fp16 ----
__device__ __forceinline__ void mma_f16(float d[4], const u32 a[4], u32 b0, u32 b1) {
    asm volatile(
        "mma.sync.aligned.m16n8k16.row.col.f32.f16.f16.f32 "
        "{%0,%1,%2,%3}, {%4,%5,%6,%7}, {%8,%9}, {%0,%1,%2,%3};"
        : "+f"(d[0]), "+f"(d[1]), "+f"(d[2]), "+f"(d[3])
        : "r"(a[0]), "r"(a[1]), "r"(a[2]), "r"(a[3]), "r"(b0), "r"(b1));
}
__device__ __forceinline__ u32 packh2(float lo, float hi) {
    __half2 v = __floats2half2_rn(lo, hi);
    return *(u32*)&v;
}
__device__ __forceinline__ void split2h(float v0, float v1, u32 &hp, u32 &lp) {
    float h0 = __half2float(__float2half_rn(v0));
    float h1 = __half2float(__float2half_rn(v1));
    hp = packh2(h0, h1);
    lp = packh2(v0 - h0, v1 - h1);
}

// ---- bf16 helpers (qkv/proj GEMMs) ----
__device__ __forceinline__ void mma_bf16(float d[4], const u32 a[4], u32 b0, u32 b1) {
    asm volatile(
        "mma.sync.aligned.m16n8k16.row.col.f32.bf16.bf16.f32 "
        "{%0,%1,%2,%3}, {%4,%5,%6,%7}, {%8,%9}, {%0,%1,%2,%3};"
        : "+f"(d[0]), "+f"(d[1]), "+f"(d[2]), "+f"(d[3])
        : "r"(a[0]), "r"(a[1]), "r"(a[2]), "r"(a[3]), "r"(b0), "r"(b1));
}
__device__ __forceinline__ u32 packbf2(float lo, float hi) {
    unsigned short b0, b1;
    asm("cvt.rn.bf16.f32 %0, %1;" : "=h"(b0) : "f"(lo));
    asm("cvt.rn.bf16.f32 %0, %1;" : "=h"(b1) : "f"(hi));
    return (u32)b0 | ((u32)b1 << 16);
}
__device__ __forceinline__ float bf2f(unsigned short b) {
    u32 u = (u32)b << 16;
    return __uint_as_float(u);
}
__device__ __forceinline__ void split2(float v0, float v1, u32 &hp, u32 &lp) {
    u32 hp0 = packbf2(v0, v1);
    float h0 = bf2f((unsigned short)(hp0 & 0xffff));
    float h1 = bf2f((unsigned short)(hp0 >> 16));
    hp = hp0;
    lp = packbf2(v0 - h0, v1 - h1);
}

// ============================================================
// 1) pos softmax row stats, closed form (geometric series)
// ============================================================
__global__ void pos_stats_kernel(const float* __restrict__ Wpos,
                                 const float* __restrict__ bpos) {
    int idx = blockIdx.x * blockDim.x + threadIdx.x;
    if (idx >= HH * NN) return;
    int h = idx / NN, i = idx - h * NN;
    float W0 = Wpos[h], W1 = Wpos[HH + h], bph = bpos[h];
    float apos = W0 + W1;
    float aneg = W1 - W0;
    float fi = (float)i, fM = (float)(NN - 1 - i);
    float mi = fmaxf(0.f, fmaxf(apos * fi, aneg * fM));

    float Sp;
    if (i == 0)            Sp = 0.f;
    else if (apos > 0.f)   Sp = __expf(apos * fi - mi) * expm1f(-apos * fi) / expm1f(-apos);
    else if (apos < 0.f)   Sp = __expf(apos - mi) * expm1f(apos * fi) / expm1f(apos);
    else                   Sp = fi * __expf(-mi);

    float Sn;
    if (i == NN - 1)       Sn = 0.f;
    else if (aneg > 0.f)   Sn = __expf(aneg * fM - mi) * expm1f(-aneg * fM) / expm1f(-aneg);
    else if (aneg < 0.f)   Sn = __expf(aneg - mi) * expm1f(aneg * fM) / expm1f(aneg);
    else                   Sn = fM * __expf(-mi);

    float den = __expf(-mi) + Sp + Sn;
    g_pm[idx]   = bph + mi;
    g_pinv[idx] = 1.f / den;
}

// ============================================================
// 2) QKV GEMM on mma.sync split-bf16 (3-pass); epilogue emits
//    fp16 q (plain), k hi/lo, vT hi/lo + f32 v.
// ============================================================
__global__ void __launch_bounds__(256) qkv_tc_kernel(const float* __restrict__ x,
                                                     const float* __restrict__ Wqk,
                                                     const float* __restrict__ Wv) {
    __shared__ u32 sAh[128 * 20], sAl[128 * 20];
    __shared__ u32 sBh[64 * 20],  sBl[64 * 20];

    int tid = threadIdx.x;
    int w = tid >> 5, lane = tid & 31, g = lane >> 2, t = lane & 3;
    int m0 = blockIdx.x * 128, n0 = blockIdx.y * 64;

    const float* Wsrc; int ldw, coff;
    if (n0 < 512) { Wsrc = Wqk; ldw = 512; coff = n0; }
    else          { Wsrc = Wv;  ldw = 256; coff = n0 - 512; }

    int arow = tid >> 1, ahalf = tid & 1;
    int bn = tid & 63, bkg = tid >> 6;

    float o[8][4] = {};

    for (int kc = 0; kc < 8; kc++) {
        int k0 = kc * 32;
        __syncthreads();
        {
            const float* xs = &x[(size_t)(m0 + arow) * 256 + k0 + ahalf * 16];
            float4 f0 = *(const float4*)xs, f1 = *(const float4*)(xs + 4);
            float4 f2 = *(const float4*)(xs + 8), f3 = *(const float4*)(xs + 12);
            u32 hi[8], lo[8];
            split2(f0.x, f0.y, hi[0], lo[0]); split2(f0.z, f0.w, hi[1], lo[1]);
            split2(f1.x, f1.y, hi[2], lo[2]); split2(f1.z, f1.w, hi[3], lo[3]);
            split2(f2.x, f2.y, hi[4], lo[4]); split2(f2.z, f2.w, hi[5], lo[5]);
            split2(f3.x, f3.y, hi[6], lo[6]); split2(f3.z, f3.w, hi[7], lo[7]);
            uint4* dh = (uint4*)&sAh[arow * 20 + ahalf * 8];
            dh[0] = make_uint4(hi[0], hi[1], hi[2], hi[3]);
            dh[1] = make_uint4(hi[4], hi[5], hi[6], hi[7]);
            uint4* dl = (uint4*)&sAl[arow * 20 + ahalf * 8];
            dl[0] = make_uint4(lo[0], lo[1], lo[2], lo[3]);
            dl[1] = make_uint4(lo[4], lo[5], lo[6], lo[7]);
        }
        {
            float wv[8];
            #pragma unroll
            for (int i = 0; i < 8; i++)
                wv[i] = Wsrc[(size_t)(k0 + bkg * 8 + i) * ldw + coff + bn];
            u32 bh4[4], bl4[4];
            split2(wv[0], wv[1], bh4[0], bl4[0]);
            split2(wv[2], wv[3], bh4[1], bl4[1]);
            split2(wv[4], wv[5], bh4[2], bl4[2]);
            split2(wv[6], wv[7], bh4[3], bl4[3]);
            *(uint4*)&sBh[bn * 20 + bkg * 4] = make_uint4(bh4[0], bh4[1], bh4[2], bh4[3]);
            *(uint4*)&sBl[bn * 20 + bkg * 4] = make_uint4(bl4[0], bl4[1], bl4[2], bl4[3]);
        }
        __syncthreads();

        u32 aH[2][4], aL[2][4];
        int r0 = 16 * w + g;
        #pragma unroll
        for (int c = 0; c < 2; c++) {
            aH[c][0] = sAh[r0 * 20 + 8 * c + t];
            aH[c][1] = sAh[(r0 + 8) * 20 + 8 * c + t];
            aH[c][2] = sAh[r0 * 20 + 8 * c + t + 4];
            aH[c][3] = sAh[(r0 + 8) * 20 + 8 * c + t + 4];
            aL[c][0] = sAl[r0 * 20 + 8 * c + t];
            aL[c][1] = sAl[(r0 + 8) * 20 + 8 * c + t];
            aL[c][2] = sAl[r0 * 20 + 8 * c + t + 4];
            aL[c][3] = sAl[(r0 + 8) * 20 + 8 * c + t + 4];
        }
        #pragma unroll
        for (int j = 0; j < 8; j++) {
            #pragma unroll
            for (int c = 0; c < 2; c++) {
                int base = (8 * j + g) * 20 + 8 * c + t;
                u32 b0 = sBh[base], b1 = sBh[base + 4];
                u32 c0 = sBl[base], c1 = sBl[base + 4];
                mma_bf16(o[j], aH[c], b0, b1);
                mma_bf16(o[j], aH[c], c0, c1);
                mma_bf16(o[j], aL[c], b0, b1);
            }
        }
    }

    int row_a = m0 + 16 * w + g;
    #pragma unroll
    for (int j = 0; j < 8; j++) {
        int c = n0 + 8 * j + 2 * t;
        #pragma unroll
        for (int r = 0; r < 2; r++) {
            int m = row_a + 8 * r;
            float v0 = o[j][2 * r], v1 = o[j][2 * r + 1];
            int b = m >> 11, n = m & (NN - 1);
            if (c < 256) {
                int h = c >> 5, d0 = c & 31;
                int bh = b * HH + h;
                v0 *= SCALE; v1 *= SCALE;
                size_t ui = ((size_t)bh * NN + n) * 16 + (d0 >> 1);
                ((u32*)g_qh16)[ui] = packh2(v0, v1);
            } else if (c < 512) {
                int cc = c - 256; int h = cc >> 5, d0 = cc & 31;
                int bh = b * HH + h;
                u32 hp, lp;
                split2h(v0, v1, hp, lp);
                size_t ui = ((size_t)bh * NN + n) * 16 + (d0 >> 1);
                ((u32*)g_kh16)[ui] = hp;
                ((u32*)g_kl16)[ui] = lp;
            } else {
                int cc = c - 512; int h = cc >> 5, d0 = cc & 31;
                int bh = b * HH + h;
                *(float2*)&g_v[((size_t)bh * NN + n) * DHH + d0] = make_float2(v0, v1);
                __half h0 = __float2half_rn(v0);
                __half h1 = __float2half_rn(v1);
                size_t t0 = ((size_t)bh * DHH + d0) * NN + n;
                g_vh16[t0]      = h0;
                g_vl16[t0]      = __float2half_rn(v0 - __half2float(h0));
                g_vh16[t0 + NN] = h1;
                g_vl16[t0 + NN] = __float2half_rn(v1 - __half2float(h1));
            }
        }
    }
}

// ============================================================
// 3) POS path: blocked-parallel exponential scans, 512 threads
// ============================================================
__global__ void __launch_bounds__(512) pos_scan_kernel(const float* __restrict__ Wpos,
                                                       const float* __restrict__ bpos) {
    __shared__ float TFs[8][32], TGs[8][32], AFs[8][32], DGs[8][32];

    int bh = blockIdx.x;
    int h = bh & (HH - 1);
    int tid = threadIdx.x;
    int w = tid >> 5, lane = tid & 31;
    float apos = Wpos[h] + Wpos[HH + h];
    float aneg = Wpos[HH + h] - Wpos[h];
    bool posg = apos > 0.f, negg = aneg > 0.f;
    float rhoF = posg ? 1.f : __expf(apos);
    float rhoG = negg ? 1.f : __expf(aneg);
    float wcF = posg ? -apos : 0.f;
    float wcG = negg ? -aneg : 0.f;
    float usG = negg ? 1.f : rhoG;

    const float* vp = g_v + (size_t)bh * NN * DHH + lane;
    float* fo = g_scanF + (size_t)bh * NN * DHH + lane;
    float* go = g_scanG + (size_t)bh * NN * DHH + lane;

    if (w < 8) {
        int c0 = w * CH;
        float F = 0.f;
        for (int ib = c0; ib < c0 + CH; ib += 8) {
            float vb[8];
            #pragma unroll
            for (int u = 0; u < 8; u++) vb[u] = vp[(ib + u) * DHH];
            #pragma unroll
            for (int u = 0; u < 8; u++) {
                float uu = vb[u] * __expf(wcF * (float)(ib + u));
                F = rhoF * F + uu;
                fo[(ib + u) * DHH] = F;
            }
        }
        TFs[w][lane] = F;
    } else {
        int c0 = (w - 8) * CH;
        float G = 0.f;
        for (int ib = c0 + CH - 1; ib >= c0; ib -= 8) {
            float vb[8];
            #pragma unroll
            for (int u = 0; u < 8; u++) vb[u] = vp[(ib - u) * DHH];
            #pragma unroll
            for (int u = 0; u < 8; u++) {
                int i = ib - u;
                go[i * DHH] = G;
                float uu = usG * vb[u] * __expf(wcG * (float)(NN - 1 - i));
                G = rhoG * G + uu;
            }
        }
        TGs[w - 8][lane] = G;
    }
    __syncthreads();

    if (w == 0) {
        float fF = posg ? 1.f : __expf(apos * (float)CH);
        float A = 0.f;
        #pragma unroll
        for (int c = 0; c < 8; c++) { AFs[c][lane] = A; A = TFs[c][lane] + fF * A; }
    } else if (w == 8) {
        float fG = negg ? 1.f : __expf(aneg * (float)CH);
        float D = 0.f;
        #pragma unroll
        for (int c = 7; c >= 0; c--) { DGs[c][lane] = D; D = TGs[c][lane] + fG * D; }
    }
    __syncthreads();

    int c = w >> 1;
    int c0 = c * CH;
    int cend = c0 + CH;
    int r0 = w * 128;
    float A = AFs[c][lane];
    float D = DGs[c][lane];
    float pfc = posg ? 0.f : apos;
    float gfc = negg ? 0.f : aneg;
    float bph = bpos[h];
    float pp = fmaxf(apos, 0.f), pn = fmaxf(aneg, 0.f);
    const float* pmrow = g_pm + h * NN;
    for (int ib = r0; ib < r0 + 128; ib += 8) {
        float fb[8], gb[8], pmb[8];
        #pragma unroll
        for (int u = 0; u < 8; u++) {
            fb[u]  = fo[(ib + u) * DHH];
            gb[u]  = go[(ib + u) * DHH];
            pmb[u] = pmrow[ib + u];
        }
        #pragma unroll
        for (int u = 0; u < 8; u++) {
            int i = ib + u;
            float Fg = fb[u] + A * __expf(pfc * (float)(i - c0 + 1));
            float Gg = gb[u] + D * __expf(gfc * (float)(cend - 1 - i));
            float c1 = __expf(bph + pp * (float)i - pmb[u]);
            float c2 = __expf(bph + pn * (float)(NN - 1 - i) - pmb[u]);
            fo[i * DHH] = c1 * Fg + c2 * Gg;
        }
    }
}

// ============================================================
// 4) PATCH attention, fp16 mma.sync:
//    QK 2-pass (q plain fp16 x k hi/lo), P single fp16, PV 2-pass.
//    Round-14 conflict-free scalar-LDS layout; K/V double-buffered.
// ============================================================
__global__ void __launch_bounds__(256, 2) attn_mma_kernel(const float* __restrict__ gating) {
    __shared__ u32 QsH[128 * 20];
    __shared__ u32 KsH[2][32 * 20], KsL[2][32 * 20];
    __shared__ u32 VsH[2][32 * 20], VsL[2][32 * 20];

    int tid = threadIdx.x;
    int w = tid >> 5, lane = tid & 31, g = lane >> 2, t = lane & 3;
    int qt = blockIdx.x, hidx = blockIdx.y, b = blockIdx.z;
    int bh = b * HH + hidx;
    int q0 = qt * 128;

    const u32* gqh = (const u32*)g_qh16 + (size_t)bh * NN * 16;
    const u32* gkh = (const u32*)g_kh16 + (size_t)bh * NN * 16;
    const u32* gkl = (const u32*)g_kl16 + (size_t)bh * NN * 16;
    const u32* gvh = (const u32*)g_vh16 + (size_t)bh * DHH * (NN / 2);
    const u32* gvl = (const u32*)g_vl16 + (size_t)bh * DHH * (NN / 2);

    // stage Q [128][32] fp16
    {
        int row = tid >> 1, half = tid & 1;
        const uint4* s0 = (const uint4*)(gqh + (size_t)(q0 + row) * 16 + half * 8);
        uint4 v0 = s0[0], v1 = s0[1];
        uint4* d0 = (uint4*)&QsH[row * 20 + half * 8];
        d0[0] = v0; d0[1] = v1;
    }
    // stage K/V tile 0 into buffer 0
    int srow = tid >> 3, spp = tid & 7;
    {
        *(uint2*)&KsH[0][srow * 20 + spp * 2] = *(const uint2*)(gkh + (size_t)srow * 16 + spp * 2);
        *(uint2*)&KsL[0][srow * 20 + spp * 2] = *(const uint2*)(gkl + (size_t)srow * 16 + spp * 2);
        *(uint2*)&VsH[0][srow * 20 + spp * 2] = *(const uint2*)(gvh + (size_t)srow * (NN / 2) + spp * 2);
        *(uint2*)&VsL[0][srow * 20 + spp * 2] = *(const uint2*)(gvl + (size_t)srow * (NN / 2) + spp * 2);
    }
    __syncthreads();

    // Q fragments (constant across tiles)
    u32 aQ[2][4];
    {
        int r0 = 16 * w + g;
        #pragma unroll
        for (int c = 0; c < 2; c++) {
            aQ[c][0] = QsH[r0 * 20 + 8 * c + t];
            aQ[c][1] = QsH[(r0 + 8) * 20 + 8 * c + t];
            aQ[c][2] = QsH[r0 * 20 + 8 * c + t + 4];
            aQ[c][3] = QsH[(r0 + 8) * 20 + 8 * c + t + 4];
        }
    }

    float o[4][4] = {};
    float lp0 = 0.f, lp1 = 0.f;

    for (int kt = 0; kt < 64; kt++) {
        int buf = kt & 1;
        uint2 pkh, pkl, pvh, pvl;
        if (kt < 63) {
            int k0n = (kt + 1) * 32;
            pkh = *(const uint2*)(gkh + (size_t)(k0n + srow) * 16 + spp * 2);
            pkl = *(const uint2*)(gkl + (size_t)(k0n + srow) * 16 + spp * 2);
            pvh = *(const uint2*)(gvh + (size_t)srow * (NN / 2) + k0n / 2 + spp * 2);
            pvl = *(const uint2*)(gvl + (size_t)srow * (NN / 2) + k0n / 2 + spp * 2);
        }
        // ---- QK: S[16q x 32k], 2-pass (q x k_hi + q x k_lo) ----
        float s[4][4] = {};
        #pragma unroll
        for (int j = 0; j < 4; j++) {
            #pragma unroll
            for (int c = 0; c < 2; c++) {
                int base = (8 * j + g) * 20 + 8 * c + t;
                u32 kb0 = KsH[buf][base], kb1 = KsH[buf][base + 4];
                u32 lb0 = KsL[buf][base], lb1 = KsL[buf][base + 4];
                mma_f16(s[j], aQ[c], kb0, kb1);
                mma_f16(s[j], aQ[c], lb0, lb1);
            }
        }
        // ---- exp + P fragments (single fp16) ----
        float e[4][4];
        #pragma unroll
        for (int j = 0; j < 4; j++) {
            e[j][0] = __expf(s[j][0]); e[j][1] = __expf(s[j][1]);
            e[j][2] = __expf(s[j][2]); e[j][3] = __expf(s[j][3]);
            lp0 += e[j][0] + e[j][1];
            lp1 += e[j][2] + e[j][3];
        }
        u32 pa[2][4];
        #pragma unroll
        for (int kc = 0; kc < 2; kc++) {
            int j0 = 2 * kc, j1 = 2 * kc + 1;
            pa[kc][0] = packh2(e[j0][0], e[j0][1]);
            pa[kc][1] = packh2(e[j0][2], e[j0][3]);
            pa[kc][2] = packh2(e[j1][0], e[j1][1]);
            pa[kc][3] = packh2(e[j1][2], e[j1][3]);
        }
        // ---- PV: O[16q x 32d], 2-pass (P x Vhi + P x Vlo) ----
        #pragma unroll
        for (int jj = 0; jj < 4; jj++) {
            #pragma unroll
            for (int kc = 0; kc < 2; kc++) {
                int base = (8 * jj + g) * 20 + 8 * kc + t;
                u32 vb0 = VsH[buf][base], vb1 = VsH[buf][base + 4];
                u32 wb0 = VsL[buf][base], wb1 = VsL[buf][base + 4];
                mma_f16(o[jj], pa[kc], vb0, vb1);
                mma_f16(o[jj], pa[kc], wb0, wb1);
            }
        }
        if (kt < 63) {
            int nb = buf ^ 1;
            *(uint2*)&KsH[nb][srow * 20 + spp * 2] = pkh;
            *(uint2*)&KsL[nb][srow * 20 + spp * 2] = pkl;
            *(uint2*)&VsH[nb][srow * 20 + spp * 2] = pvh;
            *(uint2*)&VsL[nb][srow * 20 + spp * 2] = pvl;
            __syncthreads();
        }
    }

    // ---- epilogue ----
    lp0 += __shfl_xor_sync(0xffffffffu, lp0, 1);
    lp0 += __shfl_xor_sync(0xffffffffu, lp0, 2);
    lp1 += __shfl_xor_sync(0xffffffffu, lp1, 1);
    lp1 += __shfl_xor_sync(0xffffffffu, lp1, 2);

    float gv = 1.f / (1.f + __expf(-gating[hidx]));
    int row0 = q0 + 16 * w + g, row1 = row0 + 8;
    float s1a = (1.f - gv) / lp0, s1b = (1.f - gv) / lp1;
    float s2a = gv * g_pinv[hidx * NN + row0];
    float s2b = gv * g_pinv[hidx * NN + row1];

    #pragma unroll
    for (int jj = 0; jj < 4; jj++) {
        int dh = 8 * jj + 2 * t;
        float2 p0 = *(const float2*)&g_scanF[((size_t)bh * NN + row0) * DHH + dh];
        float2 p1 = *(const float2*)&g_scanF[((size_t)bh * NN + row1) * DHH + dh];
        float2 o0 = make_float2(s1a * o[jj][0] + s2a * p0.x, s1a * o[jj][1] + s2a * p0.y);
        float2 o1 = make_float2(s1b * o[jj][2] + s2b * p1.x, s1b * o[jj][3] + s2b * p1.y);
        int col = hidx * 32 + dh;
        *(float2*)&g_ctx[((size_t)b * NN + row0) * CC + col] = o0;
        *(float2*)&g_ctx[((size_t)b * NN + row1) * CC + col] = o1;
    }
}

// ============================================================
// 5) Output projection on mma.sync split-bf16 (3-pass)
// ============================================================
__global__ void __launch_bounds__(256) proj_tc_kernel(const float* __restrict__ Wp,
                                                      const float* __restrict__ bp,
                                                      float* __restrict__ out) {
    __shared__ u32 sAh[128 * 20], sAl[128 * 20];
    __shared__ u32 sBh[64 * 20],  sBl[64 * 20];

    int tid = threadIdx.x;
    int w = tid >> 5, lane = tid & 31, g = lane >> 2, t = lane & 3;
    int m0 = blockIdx.x * 128, n0 = blockIdx.y * 64;

    int arow = tid >> 1, ahalf = tid & 1;
    int bn = tid & 63, bkg = tid >> 6;

    float o[8][4] = {};

    for (int kc = 0; kc < 8; kc++) {
        int k0 = kc * 32;
        __syncthreads();
        {
            const float* xs = &g_ctx[(size_t)(m0 + arow) * 256 + k0 + ahalf * 16];
            float4 f0 = *(const float4*)xs, f1 = *(const float4*)(xs + 4);
            float4 f2 = *(const float4*)(xs + 8), f3 = *(const float4*)(xs + 12);
            u32 hi[8], lo[8];
            split2(f0.x, f0.y, hi[0], lo[0]); split2(f0.z, f0.w, hi[1], lo[1]);
            split2(f1.x, f1.y, hi[2], lo[2]); split2(f1.z, f1.w, hi[3], lo[3]);
            split2(f2.x, f2.y, hi[4], lo[4]); split2(f2.z, f2.w, hi[5], lo[5]);
            split2(f3.x, f3.y, hi[6], lo[6]); split2(f3.z, f3.w, hi[7], lo[7]);
            uint4* dh = (uint4*)&sAh[arow * 20 + ahalf * 8];
            dh[0] = make_uint4(hi[0], hi[1], hi[2], hi[3]);
            dh[1] = make_uint4(hi[4], hi[5], hi[6], hi[7]);
            uint4* dl = (uint4*)&sAl[arow * 20 + ahalf * 8];
            dl[0] = make_uint4(lo[0], lo[1], lo[2], lo[3]);
            dl[1] = make_uint4(lo[4], lo[5], lo[6], lo[7]);
        }
        {
            float wv[8];
            #pragma unroll
            for (int i = 0; i < 8; i++)
                wv[i] = Wp[(size_t)(k0 + bkg * 8 + i) * 256 + n0 + bn];
            u32 bh4[4], bl4[4];
            split2(wv[0], wv[1], bh4[0], bl4[0]);
            split2(wv[2], wv[3], bh4[1], bl4[1]);
            split2(wv[4], wv[5], bh4[2], bl4[2]);
            split2(wv[6], wv[7], bh4[3], bl4[3]);
            *(uint4*)&sBh[bn * 20 + bkg * 4] = make_uint4(bh4[0], bh4[1], bh4[2], bh4[3]);
            *(uint4*)&sBl[bn * 20 + bkg * 4] = make_uint4(bl4[0], bl4[1], bl4[2], bl4[3]);
        }
        __syncthreads();

        u32 aH[2][4], aL[2][4];
        int r0 = 16 * w + g;
        #pragma unroll
        for (int c = 0; c < 2; c++) {
            aH[c][0] = sAh[r0 * 20 + 8 * c + t];
            aH[c][1] = sAh[(r0 + 8) * 20 + 8 * c + t];
            aH[c][2] = sAh[r0 * 20 + 8 * c + t + 4];
            aH[c][3] = sAh[(r0 + 8) * 20 + 8 * c + t + 4];
            aL[c][0] = sAl[r0 * 20 + 8 * c + t];
            aL[c][1] = sAl[(r0 + 8) * 20 + 8 * c + t];
            aL[c][2] = sAl[r0 * 20 + 8 * c + t + 4];
            aL[c][3] = sAl[(r0 + 8) * 20 + 8 * c + t + 4];
        }
        #pragma unroll
        for (int j = 0; j < 8; j++) {
            #pragma unroll
            for (int c = 0; c < 2; c++) {
                int base = (8 * j + g) * 20 + 8 * c + t;
                u32 b0 = sBh[base], b1 = sBh[base + 4];
                u32 c0 = sBl[base], c1 = sBl[base + 4];
                mma_bf16(o[j], aH[c], b0, b1);
                mma_bf16(o[j], aH[c], c0, c1);
                mma_bf16(o[j], aL[c], b0, b1);
            }
        }
    }

    int row_a = m0 + 16 * w + g;
    #pragma unroll
    for (int j = 0; j < 8; j++) {
        int c = n0 + 8 * j + 2 * t;
        float2 bpc = *(const float2*)&bp[c];
        #pragma unroll
        for (int r = 0; r < 2; r++) {
            int m = row_a + 8 * r;
            *(float2*)&out[(size_t)m * 256 + c] =
                make_float2(o[j][2 * r] + bpc.x, o[j][2 * r + 1] + bpc.y);
        }
    }
}

// ============================================================
extern "C" void kernel_launch(void* const* d_in, const int* in_sizes, int n_in,
                              void* d_out, int out_size) {
    const float* x     = (const float*)d_in[0];
    const float* Wqk   = (const float*)d_in[1];
    const float* Wv    = (const float*)d_in[2];
    const float* Wproj = (const float*)d_in[3];
    const float* bproj = (const float*)d_in[4];
    const float* Wpos  = (const float*)d_in[5];
    const float* bpos  = (const float*)d_in[6];
    const float* gate  = (const float*)d_in[7];
    float* out = (float*)d_out;

    pos_stats_kernel<<<(HH * NN + 255) / 256, 256>>>(Wpos, bpos);
    qkv_tc_kernel<<<dim3(BB * NN / 128, 12), 256>>>(x, Wqk, Wv);
    pos_scan_kernel<<<BB * HH, 512>>>(Wpos, bpos);
    attn_mma_kernel<<<dim3(NN / 128, HH, BB), 256>>>(gate);
    proj_tc_kernel<<<dim3(BB * NN / 128, 4), 256>>>(Wproj, bproj, out);
}

// round 17
// speedup vs baseline: 1.4114x; 1.2201x over previous
#include <cuda_runtime.h>
#include <cuda_fp16.h>
#include <math.h>

#define BB 2
#define NN 2048
#define CC 256
#define HH 8
#define DHH 32
#define SCALE 0.17677669529663687f  // 1/sqrt(32)
#define CH 256                       // scan chunk size (NN/8)

typedef unsigned long long u64;
typedef unsigned u32;

// ---- scratch ----
__device__ __half g_qh16[BB*HH*NN*DHH];  // [bh][n][d] fp16, pre-scaled
__device__ __half g_kh16[BB*HH*NN*DHH];  // [bh][n][d] fp16
__device__ __half g_vh16[BB*HH*DHH*NN];  // [bh][d][n] fp16 (transposed)
__device__ float g_v [BB*HH*NN*DHH];     // [bh][n][d] f32 (scan input)
__device__ float g_ctx[BB*NN*CC];
__device__ float g_pm[HH*NN];
__device__ float g_pinv[HH*NN];
__device__ float g_scanF[BB*HH*NN*DHH];
__device__ float g_scanG[BB*HH*NN*DHH];

// ---- mma.sync fp16 ----
__device__ __forceinline__ void mma_f16(float d[4], const u32 a[4], u32 b0, u32 b1) {
    asm volatile(
        "mma.sync.aligned.m16n8k16.row.col.f32.f16.f16.f32 "
        "{%0,%1,%2,%3}, {%4,%5,%6,%7}, {%8,%9}, {%0,%1,%2,%3};"
        : "+f"(d[0]), "+f"(d[1]), "+f"(d[2]), "+f"(d[3])
        : "r"(a[0]), "r"(a[1]), "r"(a[2]), "r"(a[3]), "r"(b0), "r"(b1));
}
__device__ __forceinline__ u32 packh2(float lo, float hi) {
    __half2 v = __floats2half2_rn(lo, hi);
    return *(u32*)&v;
}

// ---- bf16 helpers (qkv/proj GEMMs) ----
__device__ __forceinline__ void mma_bf16(float d[4], const u32 a[4], u32 b0, u32 b1) {
    asm volatile(
        "mma.sync.aligned.m16n8k16.row.col.f32.bf16.bf16.f32 "
        "{%0,%1,%2,%3}, {%4,%5,%6,%7}, {%8,%9}, {%0,%1,%2,%3};"
        : "+f"(d[0]), "+f"(d[1]), "+f"(d[2]), "+f"(d[3])
        : "r"(a[0]), "r"(a[1]), "r"(a[2]), "r"(a[3]), "r"(b0), "r"(b1));
}
__device__ __forceinline__ u32 packbf2(float lo, float hi) {
    unsigned short b0, b1;
    asm("cvt.rn.bf16.f32 %0, %1;" : "=h"(b0) : "f"(lo));
    asm("cvt.rn.bf16.f32 %0, %1;" : "=h"(b1) : "f"(hi));
    return (u32)b0 | ((u32)b1 << 16);
}
__device__ __forceinline__ float bf2f(unsigned short b) {
    u32 u = (u32)b << 16;
    return __uint_as_float(u);
}
__device__ __forceinline__ void split2(float v0, float v1, u32 &hp, u32 &lp) {
    u32 hp0 = packbf2(v0, v1);
    float h0 = bf2f((unsigned short)(hp0 & 0xffff));
    float h1 = bf2f((unsigned short)(hp0 >> 16));
    hp = hp0;
    lp = packbf2(v0 - h0, v1 - h1);
}

// ============================================================
// 1) pos softmax row stats, closed form (geometric series)
// ============================================================
__global__ void pos_stats_kernel(const float* __restrict__ Wpos,
                                 const float* __restrict__ bpos) {
    int idx = blockIdx.x * blockDim.x + threadIdx.x;
    if (idx >= HH * NN) return;
    int h = idx / NN, i = idx - h * NN;
    float W0 = Wpos[h], W1 = Wpos[HH + h], bph = bpos[h];
    float apos = W0 + W1;
    float aneg = W1 - W0;
    float fi = (float)i, fM = (float)(NN - 1 - i);
    float mi = fmaxf(0.f, fmaxf(apos * fi, aneg * fM));

    float Sp;
    if (i == 0)            Sp = 0.f;
    else if (apos > 0.f)   Sp = __expf(apos * fi - mi) * expm1f(-apos * fi) / expm1f(-apos);
    else if (apos < 0.f)   Sp = __expf(apos - mi) * expm1f(apos * fi) / expm1f(apos);
    else                   Sp = fi * __expf(-mi);

    float Sn;
    if (i == NN - 1)       Sn = 0.f;
    else if (aneg > 0.f)   Sn = __expf(aneg * fM - mi) * expm1f(-aneg * fM) / expm1f(-aneg);
    else if (aneg < 0.f)   Sn = __expf(aneg - mi) * expm1f(aneg * fM) / expm1f(aneg);
    else                   Sn = fM * __expf(-mi);

    float den = __expf(-mi) + Sp + Sn;
    g_pm[idx]   = bph + mi;
    g_pinv[idx] = 1.f / den;
}

// ============================================================
// 2) QKV GEMM on mma.sync split-bf16 (3-pass); epilogue emits
//    plain fp16 q, k, vT + f32 v.
// ============================================================
__global__ void __launch_bounds__(256) qkv_tc_kernel(const float* __restrict__ x,
                                                     const float* __restrict__ Wqk,
                                                     const float* __restrict__ Wv) {
    __shared__ u32 sAh[128 * 20], sAl[128 * 20];
    __shared__ u32 sBh[64 * 20],  sBl[64 * 20];

    int tid = threadIdx.x;
    int w = tid >> 5, lane = tid & 31, g = lane >> 2, t = lane & 3;
    int m0 = blockIdx.x * 128, n0 = blockIdx.y * 64;

    const float* Wsrc; int ldw, coff;
    if (n0 < 512) { Wsrc = Wqk; ldw = 512; coff = n0; }
    else          { Wsrc = Wv;  ldw = 256; coff = n0 - 512; }

    int arow = tid >> 1, ahalf = tid & 1;
    int bn = tid & 63, bkg = tid >> 6;

    float o[8][4] = {};

    for (int kc = 0; kc < 8; kc++) {
        int k0 = kc * 32;
        __syncthreads();
        {
            const float* xs = &x[(size_t)(m0 + arow) * 256 + k0 + ahalf * 16];
            float4 f0 = *(const float4*)xs, f1 = *(const float4*)(xs + 4);
            float4 f2 = *(const float4*)(xs + 8), f3 = *(const float4*)(xs + 12);
            u32 hi[8], lo[8];
            split2(f0.x, f0.y, hi[0], lo[0]); split2(f0.z, f0.w, hi[1], lo[1]);
            split2(f1.x, f1.y, hi[2], lo[2]); split2(f1.z, f1.w, hi[3], lo[3]);
            split2(f2.x, f2.y, hi[4], lo[4]); split2(f2.z, f2.w, hi[5], lo[5]);
            split2(f3.x, f3.y, hi[6], lo[6]); split2(f3.z, f3.w, hi[7], lo[7]);
            uint4* dh = (uint4*)&sAh[arow * 20 + ahalf * 8];
            dh[0] = make_uint4(hi[0], hi[1], hi[2], hi[3]);
            dh[1] = make_uint4(hi[4], hi[5], hi[6], hi[7]);
            uint4* dl = (uint4*)&sAl[arow * 20 + ahalf * 8];
            dl[0] = make_uint4(lo[0], lo[1], lo[2], lo[3]);
            dl[1] = make_uint4(lo[4], lo[5], lo[6], lo[7]);
        }
        {
            float wv[8];
            #pragma unroll
            for (int i = 0; i < 8; i++)
                wv[i] = Wsrc[(size_t)(k0 + bkg * 8 + i) * ldw + coff + bn];
            u32 bh4[4], bl4[4];
            split2(wv[0], wv[1], bh4[0], bl4[0]);
            split2(wv[2], wv[3], bh4[1], bl4[1]);
            split2(wv[4], wv[5], bh4[2], bl4[2]);
            split2(wv[6], wv[7], bh4[3], bl4[3]);
            *(uint4*)&sBh[bn * 20 + bkg * 4] = make_uint4(bh4[0], bh4[1], bh4[2], bh4[3]);
            *(uint4*)&sBl[bn * 20 + bkg * 4] = make_uint4(bl4[0], bl4[1], bl4[2], bl4[3]);
        }
        __syncthreads();

        u32 aH[2][4], aL[2][4];
        int r0 = 16 * w + g;
        #pragma unroll
        for (int c = 0; c < 2; c++) {
            aH[c][0] = sAh[r0 * 20 + 8 * c + t];
            aH[c][1] = sAh[(r0 + 8) * 20 + 8 * c + t];
            aH[c][2] = sAh[r0 * 20 + 8 * c + t + 4];
            aH[c][3] = sAh[(r0 + 8) * 20 + 8 * c + t + 4];
            aL[c][0] = sAl[r0 * 20 + 8 * c + t];
            aL[c][1] = sAl[(r0 + 8) * 20 + 8 * c + t];
            aL[c][2] = sAl[r0 * 20 + 8 * c + t + 4];
            aL[c][3] = sAl[(r0 + 8) * 20 + 8 * c + t + 4];
        }
        #pragma unroll
        for (int j = 0; j < 8; j++) {
            #pragma unroll
            for (int c = 0; c < 2; c++) {
                int base = (8 * j + g) * 20 + 8 * c + t;
                u32 b0 = sBh[base], b1 = sBh[base + 4];
                u32 c0 = sBl[base], c1 = sBl[base + 4];
                mma_bf16(o[j], aH[c], b0, b1);
                mma_bf16(o[j], aH[c], c0, c1);
                mma_bf16(o[j], aL[c], b0, b1);
            }
        }
    }

    int row_a = m0 + 16 * w + g;
    #pragma unroll
    for (int j = 0; j < 8; j++) {
        int c = n0 + 8 * j + 2 * t;
        #pragma unroll
        for (int r = 0; r < 2; r++) {
            int m = row_a + 8 * r;
            float v0 = o[j][2 * r], v1 = o[j][2 * r + 1];
            int b = m >> 11, n = m & (NN - 1);
            if (c < 256) {
                int h = c >> 5, d0 = c & 31;
                int bh = b * HH + h;
                v0 *= SCALE; v1 *= SCALE;
                size_t ui = ((size_t)bh * NN + n) * 16 + (d0 >> 1);
                ((u32*)g_qh16)[ui] = packh2(v0, v1);
            } else if (c < 512) {
                int cc = c - 256; int h = cc >> 5, d0 = cc & 31;
                int bh = b * HH + h;
                size_t ui = ((size_t)bh * NN + n) * 16 + (d0 >> 1);
                ((u32*)g_kh16)[ui] = packh2(v0, v1);
            } else {
                int cc = c - 512; int h = cc >> 5, d0 = cc & 31;
                int bh = b * HH + h;
                *(float2*)&g_v[((size_t)bh * NN + n) * DHH + d0] = make_float2(v0, v1);
                size_t t0 = ((size_t)bh * DHH + d0) * NN + n;
                g_vh16[t0]      = __float2half_rn(v0);
                g_vh16[t0 + NN] = __float2half_rn(v1);
            }
        }
    }
}

// ============================================================
// 3) POS path: blocked-parallel exponential scans, 512 threads
// ============================================================
__global__ void __launch_bounds__(512) pos_scan_kernel(const float* __restrict__ Wpos,
                                                       const float* __restrict__ bpos) {
    __shared__ float TFs[8][32], TGs[8][32], AFs[8][32], DGs[8][32];

    int bh = blockIdx.x;
    int h = bh & (HH - 1);
    int tid = threadIdx.x;
    int w = tid >> 5, lane = tid & 31;
    float apos = Wpos[h] + Wpos[HH + h];
    float aneg = Wpos[HH + h] - Wpos[h];
    bool posg = apos > 0.f, negg = aneg > 0.f;
    float rhoF = posg ? 1.f : __expf(apos);
    float rhoG = negg ? 1.f : __expf(aneg);
    float wcF = posg ? -apos : 0.f;
    float wcG = negg ? -aneg : 0.f;
    float usG = negg ? 1.f : rhoG;

    const float* vp = g_v + (size_t)bh * NN * DHH + lane;
    float* fo = g_scanF + (size_t)bh * NN * DHH + lane;
    float* go = g_scanG + (size_t)bh * NN * DHH + lane;

    if (w < 8) {
        int c0 = w * CH;
        float F = 0.f;
        for (int ib = c0; ib < c0 + CH; ib += 8) {
            float vb[8];
            #pragma unroll
            for (int u = 0; u < 8; u++) vb[u] = vp[(ib + u) * DHH];
            #pragma unroll
            for (int u = 0; u < 8; u++) {
                float uu = vb[u] * __expf(wcF * (float)(ib + u));
                F = rhoF * F + uu;
                fo[(ib + u) * DHH] = F;
            }
        }
        TFs[w][lane] = F;
    } else {
        int c0 = (w - 8) * CH;
        float G = 0.f;
        for (int ib = c0 + CH - 1; ib >= c0; ib -= 8) {
            float vb[8];
            #pragma unroll
            for (int u = 0; u < 8; u++) vb[u] = vp[(ib - u) * DHH];
            #pragma unroll
            for (int u = 0; u < 8; u++) {
                int i = ib - u;
                go[i * DHH] = G;
                float uu = usG * vb[u] * __expf(wcG * (float)(NN - 1 - i));
                G = rhoG * G + uu;
            }
        }
        TGs[w - 8][lane] = G;
    }
    __syncthreads();

    if (w == 0) {
        float fF = posg ? 1.f : __expf(apos * (float)CH);
        float A = 0.f;
        #pragma unroll
        for (int c = 0; c < 8; c++) { AFs[c][lane] = A; A = TFs[c][lane] + fF * A; }
    } else if (w == 8) {
        float fG = negg ? 1.f : __expf(aneg * (float)CH);
        float D = 0.f;
        #pragma unroll
        for (int c = 7; c >= 0; c--) { DGs[c][lane] = D; D = TGs[c][lane] + fG * D; }
    }
    __syncthreads();

    int c = w >> 1;
    int c0 = c * CH;
    int cend = c0 + CH;
    int r0 = w * 128;
    float A = AFs[c][lane];
    float D = DGs[c][lane];
    float pfc = posg ? 0.f : apos;
    float gfc = negg ? 0.f : aneg;
    float bph = bpos[h];
    float pp = fmaxf(apos, 0.f), pn = fmaxf(aneg, 0.f);
    const float* pmrow = g_pm + h * NN;
    for (int ib = r0; ib < r0 + 128; ib += 8) {
        float fb[8], gb[8], pmb[8];
        #pragma unroll
        for (int u = 0; u < 8; u++) {
            fb[u]  = fo[(ib + u) * DHH];
            gb[u]  = go[(ib + u) * DHH];
            pmb[u] = pmrow[ib + u];
        }
        #pragma unroll
        for (int u = 0; u < 8; u++) {
            int i = ib + u;
            float Fg = fb[u] + A * __expf(pfc * (float)(i - c0 + 1));
            float Gg = gb[u] + D * __expf(gfc * (float)(cend - 1 - i));
            float c1 = __expf(bph + pp * (float)i - pmb[u]);
            float c2 = __expf(bph + pn * (float)(NN - 1 - i) - pmb[u]);
            fo[i * DHH] = c1 * Fg + c2 * Gg;
        }
    }
}

// ============================================================
// 4) PATCH attention, plain fp16 mma.sync (QK 1-pass, PV 1-pass).
//    Conflict-free scalar-LDS layout; K/V double-buffered.
// ============================================================
__global__ void __launch_bounds__(256, 2) attn_mma_kernel(const float* __restrict__ gating) {
    __shared__ u32 QsH[128 * 20];
    __shared__ u32 KsH[2][32 * 20];
    __shared__ u32 VsH[2][32 * 20];

    int tid = threadIdx.x;
    int w = tid >> 5, lane = tid & 31, g = lane >> 2, t = lane & 3;
    int qt = blockIdx.x, hidx = blockIdx.y, b = blockIdx.z;
    int bh = b * HH + hidx;
    int q0 = qt * 128;

    const u32* gqh = (const u32*)g_qh16 + (size_t)bh * NN * 16;
    const u32* gkh = (const u32*)g_kh16 + (size_t)bh * NN * 16;
    const u32* gvh = (const u32*)g_vh16 + (size_t)bh * DHH * (NN / 2);

    // stage Q [128][32] fp16
    {
        int row = tid >> 1, half = tid & 1;
        const uint4* s0 = (const uint4*)(gqh + (size_t)(q0 + row) * 16 + half * 8);
        uint4 v0 = s0[0], v1 = s0[1];
        uint4* d0 = (uint4*)&QsH[row * 20 + half * 8];
        d0[0] = v0; d0[1] = v1;
    }
    // stage K/V tile 0 into buffer 0
    int srow = tid >> 3, spp = tid & 7;
    {
        *(uint2*)&KsH[0][srow * 20 + spp * 2] = *(const uint2*)(gkh + (size_t)srow * 16 + spp * 2);
        *(uint2*)&VsH[0][srow * 20 + spp * 2] = *(const uint2*)(gvh + (size_t)srow * (NN / 2) + spp * 2);
    }
    __syncthreads();

    // Q fragments (constant across tiles)
    u32 aQ[2][4];
    {
        int r0 = 16 * w + g;
        #pragma unroll
        for (int c = 0; c < 2; c++) {
            aQ[c][0] = QsH[r0 * 20 + 8 * c + t];
            aQ[c][1] = QsH[(r0 + 8) * 20 + 8 * c + t];
            aQ[c][2] = QsH[r0 * 20 + 8 * c + t + 4];
            aQ[c][3] = QsH[(r0 + 8) * 20 + 8 * c + t + 4];
        }
    }

    float o[4][4] = {};
    float lp0 = 0.f, lp1 = 0.f;

    for (int kt = 0; kt < 64; kt++) {
        int buf = kt & 1;
        uint2 pkh, pvh;
        if (kt < 63) {
            int k0n = (kt + 1) * 32;
            pkh = *(const uint2*)(gkh + (size_t)(k0n + srow) * 16 + spp * 2);
            pvh = *(const uint2*)(gvh + (size_t)srow * (NN / 2) + k0n / 2 + spp * 2);
        }
        // ---- QK: S[16q x 32k], 1-pass fp16 ----
        float s[4][4] = {};
        #pragma unroll
        for (int j = 0; j < 4; j++) {
            #pragma unroll
            for (int c = 0; c < 2; c++) {
                int base = (8 * j + g) * 20 + 8 * c + t;
                u32 kb0 = KsH[buf][base], kb1 = KsH[buf][base + 4];
                mma_f16(s[j], aQ[c], kb0, kb1);
            }
        }
        // ---- exp + P fragments ----
        float e[4][4];
        #pragma unroll
        for (int j = 0; j < 4; j++) {
            e[j][0] = __expf(s[j][0]); e[j][1] = __expf(s[j][1]);
            e[j][2] = __expf(s[j][2]); e[j][3] = __expf(s[j][3]);
            lp0 += e[j][0] + e[j][1];
            lp1 += e[j][2] + e[j][3];
        }
        u32 pa[2][4];
        #pragma unroll
        for (int kc = 0; kc < 2; kc++) {
            int j0 = 2 * kc, j1 = 2 * kc + 1;
            pa[kc][0] = packh2(e[j0][0], e[j0][1]);
            pa[kc][1] = packh2(e[j0][2], e[j0][3]);
            pa[kc][2] = packh2(e[j1][0], e[j1][1]);
            pa[kc][3] = packh2(e[j1][2], e[j1][3]);
        }
        // ---- PV: O[16q x 32d], 1-pass ----
        #pragma unroll
        for (int jj = 0; jj < 4; jj++) {
            #pragma unroll
            for (int kc = 0; kc < 2; kc++) {
                int base = (8 * jj + g) * 20 + 8 * kc + t;
                u32 vb0 = VsH[buf][base], vb1 = VsH[buf][base + 4];
                mma_f16(o[jj], pa[kc], vb0, vb1);
            }
        }
        if (kt < 63) {
            int nb = buf ^ 1;
            *(uint2*)&KsH[nb][srow * 20 + spp * 2] = pkh;
            *(uint2*)&VsH[nb][srow * 20 + spp * 2] = pvh;
            __syncthreads();
        }
    }

    // ---- epilogue ----
    lp0 += __shfl_xor_sync(0xffffffffu, lp0, 1);
    lp0 += __shfl_xor_sync(0xffffffffu, lp0, 2);
    lp1 += __shfl_xor_sync(0xffffffffu, lp1, 1);
    lp1 += __shfl_xor_sync(0xffffffffu, lp1, 2);

    float gv = 1.f / (1.f + __expf(-gating[hidx]));
    int row0 = q0 + 16 * w + g, row1 = row0 + 8;
    float s1a = (1.f - gv) / lp0, s1b = (1.f - gv) / lp1;
    float s2a = gv * g_pinv[hidx * NN + row0];
    float s2b = gv * g_pinv[hidx * NN + row1];

    #pragma unroll
    for (int jj = 0; jj < 4; jj++) {
        int dh = 8 * jj + 2 * t;
        float2 p0 = *(const float2*)&g_scanF[((size_t)bh * NN + row0) * DHH + dh];
        float2 p1 = *(const float2*)&g_scanF[((size_t)bh * NN + row1) * DHH + dh];
        float2 o0 = make_float2(s1a * o[jj][0] + s2a * p0.x, s1a * o[jj][1] + s2a * p0.y);
        float2 o1 = make_float2(s1b * o[jj][2] + s2b * p1.x, s1b * o[jj][3] + s2b * p1.y);
        int col = hidx * 32 + dh;
        *(float2*)&g_ctx[((size_t)b * NN + row0) * CC + col] = o0;
        *(float2*)&g_ctx[((size_t)b * NN + row1) * CC + col] = o1;
    }
}

// ============================================================
// 5) Output projection on mma.sync split-bf16 (3-pass)
// ============================================================
__global__ void __launch_bounds__(256) proj_tc_kernel(const float* __restrict__ Wp,
                                                      const float* __restrict__ bp,
                                                      float* __restrict__ out) {
    __shared__ u32 sAh[128 * 20], sAl[128 * 20];
    __shared__ u32 sBh[64 * 20],  sBl[64 * 20];

    int tid = threadIdx.x;
    int w = tid >> 5, lane = tid & 31, g = lane >> 2, t = lane & 3;
    int m0 = blockIdx.x * 128, n0 = blockIdx.y * 64;

    int arow = tid >> 1, ahalf = tid & 1;
    int bn = tid & 63, bkg = tid >> 6;

    float o[8][4] = {};

    for (int kc = 0; kc < 8; kc++) {
        int k0 = kc * 32;
        __syncthreads();
        {
            const float* xs = &g_ctx[(size_t)(m0 + arow) * 256 + k0 + ahalf * 16];
            float4 f0 = *(const float4*)xs, f1 = *(const float4*)(xs + 4);
            float4 f2 = *(const float4*)(xs + 8), f3 = *(const float4*)(xs + 12);
            u32 hi[8], lo[8];
            split2(f0.x, f0.y, hi[0], lo[0]); split2(f0.z, f0.w, hi[1], lo[1]);
            split2(f1.x, f1.y, hi[2], lo[2]); split2(f1.z, f1.w, hi[3], lo[3]);
            split2(f2.x, f2.y, hi[4], lo[4]); split2(f2.z, f2.w, hi[5], lo[5]);
            split2(f3.x, f3.y, hi[6], lo[6]); split2(f3.z, f3.w, hi[7], lo[7]);
            uint4* dh = (uint4*)&sAh[arow * 20 + ahalf * 8];
            dh[0] = make_uint4(hi[0], hi[1], hi[2], hi[3]);
            dh[1] = make_uint4(hi[4], hi[5], hi[6], hi[7]);
            uint4* dl = (uint4*)&sAl[arow * 20 + ahalf * 8];
            dl[0] = make_uint4(lo[0], lo[1], lo[2], lo[3]);
            dl[1] = make_uint4(lo[4], lo[5], lo[6], lo[7]);
        }
        {
            float wv[8];
            #pragma unroll
            for (int i = 0; i < 8; i++)
                wv[i] = Wp[(size_t)(k0 + bkg * 8 + i) * 256 + n0 + bn];
            u32 bh4[4], bl4[4];
            split2(wv[0], wv[1], bh4[0], bl4[0]);
            split2(wv[2], wv[3], bh4[1], bl4[1]);
            split2(wv[4], wv[5], bh4[2], bl4[2]);
            split2(wv[6], wv[7], bh4[3], bl4[3]);
            *(uint4*)&sBh[bn * 20 + bkg * 4] = make_uint4(bh4[0], bh4[1], bh4[2], bh4[3]);
            *(uint4*)&sBl[bn * 20 + bkg * 4] = make_uint4(bl4[0], bl4[1], bl4[2], bl4[3]);
        }
        __syncthreads();

        u32 aH[2][4], aL[2][4];
        int r0 = 16 * w + g;
        #pragma unroll
        for (int c = 0; c < 2; c++) {
            aH[c][0] = sAh[r0 * 20 + 8 * c + t];
            aH[c][1] = sAh[(r0 + 8) * 20 + 8 * c + t];
            aH[c][2] = sAh[r0 * 20 + 8 * c + t + 4];
            aH[c][3] = sAh[(r0 + 8) * 20 + 8 * c + t + 4];
            aL[c][0] = sAl[r0 * 20 + 8 * c + t];
            aL[c][1] = sAl[(r0 + 8) * 20 + 8 * c + t];
            aL[c][2] = sAl[r0 * 20 + 8 * c + t + 4];
            aL[c][3] = sAl[(r0 + 8) * 20 + 8 * c + t + 4];
        }
        #pragma unroll
        for (int j = 0; j < 8; j++) {
            #pragma unroll
            for (int c = 0; c < 2; c++) {
                int base = (8 * j + g) * 20 + 8 * c + t;
                u32 b0 = sBh[base], b1 = sBh[base + 4];
                u32 c0 = sBl[base], c1 = sBl[base + 4];
                mma_bf16(o[j], aH[c], b0, b1);
                mma_bf16(o[j], aH[c], c0, c1);
                mma_bf16(o[j], aL[c], b0, b1);
            }
        }
    }

    int row_a = m0 + 16 * w + g;
    #pragma unroll
    for (int j = 0; j < 8; j++) {
        int c = n0 + 8 * j + 2 * t;
        float2 bpc = *(const float2*)&bp[c];
        #pragma unroll
        for (int r = 0; r < 2; r++) {
            int m = row_a + 8 * r;
            *(float2*)&out[(size_t)m * 256 + c] =
                make_float2(o[j][2 * r] + bpc.x, o[j][2 * r + 1] + bpc.y);
        }
    }
}

// ============================================================
extern "C" void kernel_launch(void* const* d_in, const int* in_sizes, int n_in,
                              void* d_out, int out_size) {
    const float* x     = (const float*)d_in[0];
    const float* Wqk   = (const float*)d_in[1];
    const float* Wv    = (const float*)d_in[2];
    const float* Wproj = (const float*)d_in[3];
    const float* bproj = (const float*)d_in[4];
    const float* Wpos  = (const float*)d_in[5];
    const float* bpos  = (const float*)d_in[6];
    const float* gate  = (const float*)d_in[7];
    float* out = (float*)d_out;

    pos_stats_kernel<<<(HH * NN + 255) / 256, 256>>>(Wpos, bpos);
    qkv_tc_kernel<<<dim3(BB * NN / 128, 12), 256>>>(x, Wqk, Wv);
    pos_scan_kernel<<<BB * HH, 512>>>(Wpos, bpos);
    attn_mma_kernel<<<dim3(NN / 128, HH, BB), 256>>>(gate);
    proj_tc_kernel<<<dim3(BB * NN / 128, 4), 256>>>(Wproj, bproj, out);
}